// round 14
// baseline (speedup 1.0000x reference)
#include <cuda_runtime.h>
#include <cuda_bf16.h>
#include <stdint.h>

// Problem constants
#define BATCH   4
#define SEQ     2048
#define EMB     512
#define HEADS   8
#define DH      64
#define MROWS   (BATCH * SEQ)     // 8192
#define NQKV    (3 * EMB)         // 1536

// ======================= scratch (__device__ globals) =========================
__device__ __nv_bfloat16 g_xh[(size_t)MROWS * EMB];
__device__ __nv_bfloat16 g_xl[(size_t)MROWS * EMB];
__device__ __nv_bfloat16 g_qkvh[(size_t)MROWS * NQKV];
__device__ __nv_bfloat16 g_qkvl[(size_t)MROWS * NQKV];
__device__ __nv_bfloat16 g_yh[(size_t)MROWS * EMB];
__device__ __nv_bfloat16 g_yl[(size_t)MROWS * EMB];
__device__ __nv_bfloat16 g_wah[(size_t)NQKV * EMB];   // W_attn^T [1536,512]
__device__ __nv_bfloat16 g_wal[(size_t)NQKV * EMB];
__device__ __nv_bfloat16 g_woh[(size_t)EMB * EMB];    // W_out^T [512,512]
__device__ __nv_bfloat16 g_wol[(size_t)EMB * EMB];

// ======================= helpers ==============================================
__device__ __forceinline__ uint32_t smem_u32(const void* p) {
    uint32_t a;
    asm("{ .reg .u64 t; cvta.to.shared.u64 t, %1; cvt.u32.u64 %0, t; }" : "=r"(a) : "l"(p));
    return a;
}
__device__ __forceinline__ void cp16(uint32_t dst, const void* src) {
    asm volatile("cp.async.cg.shared.global [%0], [%1], 16;" :: "r"(dst), "l"(src));
}
#define CP_COMMIT() asm volatile("cp.async.commit_group;" ::: "memory")
#define CP_WAIT(n)  asm volatile("cp.async.wait_group %0;" :: "n"(n) : "memory")

__device__ __forceinline__ void ldsm_x4(uint32_t* r, uint32_t addr) {
    asm volatile("ldmatrix.sync.aligned.m8n8.x4.shared.b16 {%0,%1,%2,%3}, [%4];"
                 : "=r"(r[0]), "=r"(r[1]), "=r"(r[2]), "=r"(r[3]) : "r"(addr));
}
__device__ __forceinline__ void ldsm_x4_t(uint32_t* r, uint32_t addr) {
    asm volatile("ldmatrix.sync.aligned.m8n8.x4.trans.shared.b16 {%0,%1,%2,%3}, [%4];"
                 : "=r"(r[0]), "=r"(r[1]), "=r"(r[2]), "=r"(r[3]) : "r"(addr));
}
__device__ __forceinline__ void mma_bf16(float* c, const uint32_t* a, const uint32_t* b) {
    asm volatile("mma.sync.aligned.m16n8k16.row.col.f32.bf16.bf16.f32 "
                 "{%0,%1,%2,%3}, {%4,%5,%6,%7}, {%8,%9}, {%0,%1,%2,%3};"
                 : "+f"(c[0]), "+f"(c[1]), "+f"(c[2]), "+f"(c[3])
                 : "r"(a[0]), "r"(a[1]), "r"(a[2]), "r"(a[3]), "r"(b[0]), "r"(b[1]));
}
__device__ __forceinline__ float ex2f(float x) {
    float y;
    asm("ex2.approx.f32 %0, %1;" : "=f"(y) : "f"(x));
    return y;
}
// split pair of fp32 into bf16 hi (packed) + bf16 lo residual (packed)
__device__ __forceinline__ void split2(float v0, float v1, uint32_t& hh, uint32_t& ll) {
    __nv_bfloat162 h2, l2;
    h2.x = __float2bfloat16(v0);
    h2.y = __float2bfloat16(v1);
    l2.x = __float2bfloat16(v0 - __bfloat162float(h2.x));
    l2.y = __float2bfloat16(v1 - __bfloat162float(h2.y));
    hh = *(uint32_t*)&h2;
    ll = *(uint32_t*)&l2;
}

// ======================= conversion kernels ===================================
__global__ __launch_bounds__(256) void conv_split(const float* __restrict__ in,
                                                  __nv_bfloat16* __restrict__ h,
                                                  __nv_bfloat16* __restrict__ l, int n) {
    int i = (blockIdx.x * blockDim.x + threadIdx.x) * 4;
    if (i >= n) return;
    float4 v = *(const float4*)(in + i);
    uint32_t h0, l0, h1, l1;
    split2(v.x, v.y, h0, l0);
    split2(v.z, v.w, h1, l1);
    *(uint32_t*)(h + i)     = h0;
    *(uint32_t*)(h + i + 2) = h1;
    *(uint32_t*)(l + i)     = l0;
    *(uint32_t*)(l + i + 2) = l1;
}

// W [K,N] row-major -> W^T [N,K] split hi/lo
__global__ __launch_bounds__(256) void conv_w_t(const float* __restrict__ W,
                                                __nv_bfloat16* __restrict__ Th,
                                                __nv_bfloat16* __restrict__ Tl,
                                                int K, int N) {
    int idx = blockIdx.x * blockDim.x + threadIdx.x;
    if (idx >= K * N) return;
    int n = idx / K, k = idx - n * K;
    float v = W[(size_t)k * N + n];
    __nv_bfloat16 h = __float2bfloat16(v);
    Th[idx] = h;
    Tl[idx] = __float2bfloat16(v - __bfloat162float(h));
}

// ======================= split-bf16 HMMA GEMM =================================
// C[M,N] = (Ah+Al)[M,K] @ (Bh+Bl)[N,K]^T + bias
// BM=128, BN=128, BK=32, 256 threads (8 warps: 2m x 4n, warp tile 64x32)
// smem per buffer: Ah(0) Al(10240) Bh(20480) Bl(30720), row stride 80B (40 elems)
#define GE_BUF 40960
#define GE_SMEM (2 * GE_BUF)

template<int OUT_SPLIT>
__global__ __launch_bounds__(256, 2) void hgemm(
    const __nv_bfloat16* __restrict__ Ah, const __nv_bfloat16* __restrict__ Al,
    const __nv_bfloat16* __restrict__ Bh, const __nv_bfloat16* __restrict__ Bl,
    const float* __restrict__ bias,
    float* __restrict__ C, __nv_bfloat16* __restrict__ Ch, __nv_bfloat16* __restrict__ Cl,
    int N, int K)
{
    extern __shared__ char smem[];
    const uint32_t sb = smem_u32(smem);
    const int tid = threadIdx.x;
    const int lane = tid & 31, wid = tid >> 5;
    const int bm = blockIdx.y * 128, bn = blockIdx.x * 128;
    const int wm = (wid >> 2) * 64, wn = (wid & 3) * 32;

    // ldmatrix lane geometry
    const int a_row = (lane & 7) + ((lane >> 3) & 1) * 8;
    const int a_kc  = ((lane >> 4) & 1) * 8;
    const int b_row = (lane & 7) + ((lane >> 4) & 1) * 8;
    const int b_kc  = ((lane >> 3) & 1) * 8;

    float c[4][4][4];
#pragma unroll
    for (int i = 0; i < 4; i++)
#pragma unroll
        for (int j = 0; j < 4; j++)
#pragma unroll
            for (int r = 0; r < 4; r++) c[i][j][r] = 0.0f;

    const int nstage = K >> 5;

    // stage loader
    auto load_stage = [&](int k0, int buf) {
        const uint32_t s0 = sb + buf * GE_BUF;
#pragma unroll
        for (int i = 0; i < 2; i++) {
            int cidx = tid + i * 256;        // 0..511
            int row = cidx >> 2, kc = cidx & 3;
            uint32_t doff = row * 80 + kc * 16;
            size_t ao = (size_t)(bm + row) * K + k0 + kc * 8;
            size_t bo = (size_t)(bn + row) * K + k0 + kc * 8;
            cp16(s0 + doff,         Ah + ao);
            cp16(s0 + 10240 + doff, Al + ao);
            cp16(s0 + 20480 + doff, Bh + bo);
            cp16(s0 + 30720 + doff, Bl + bo);
        }
    };

    load_stage(0, 0);
    CP_COMMIT();

    for (int s = 0; s < nstage; s++) {
        if (s + 1 < nstage) {
            load_stage((s + 1) * 32, (s + 1) & 1);
            CP_COMMIT();
            CP_WAIT(1);
        } else {
            CP_WAIT(0);
        }
        __syncthreads();
        const uint32_t s0 = sb + (s & 1) * GE_BUF;
#pragma unroll
        for (int kk = 0; kk < 2; kk++) {
            uint32_t bh[4][2], bl[4][2];
#pragma unroll
            for (int np = 0; np < 2; np++) {
                uint32_t r4[4];
                uint32_t addr = s0 + 20480 + (uint32_t)(wn + np * 16 + b_row) * 80 + (kk * 16 + b_kc) * 2;
                ldsm_x4(r4, addr);
                bh[np * 2][0] = r4[0]; bh[np * 2][1] = r4[1];
                bh[np * 2 + 1][0] = r4[2]; bh[np * 2 + 1][1] = r4[3];
                ldsm_x4(r4, addr + 10240);
                bl[np * 2][0] = r4[0]; bl[np * 2][1] = r4[1];
                bl[np * 2 + 1][0] = r4[2]; bl[np * 2 + 1][1] = r4[3];
            }
            // term-major per mf: same-accumulator reuse gap = 4 MMAs
#pragma unroll
            for (int mf = 0; mf < 4; mf++) {
                uint32_t ah[4], al[4];
                uint32_t addr = s0 + (uint32_t)(wm + mf * 16 + a_row) * 80 + (kk * 16 + a_kc) * 2;
                ldsm_x4(ah, addr);
                ldsm_x4(al, addr + 10240);
#pragma unroll
                for (int nf = 0; nf < 4; nf++) mma_bf16(c[mf][nf], ah, bh[nf]);
#pragma unroll
                for (int nf = 0; nf < 4; nf++) mma_bf16(c[mf][nf], ah, bl[nf]);
#pragma unroll
                for (int nf = 0; nf < 4; nf++) mma_bf16(c[mf][nf], al, bh[nf]);
            }
        }
        __syncthreads();
    }

    // epilogue
    const int trow = lane >> 2, tcol = (lane & 3) * 2;
#pragma unroll
    for (int mf = 0; mf < 4; mf++) {
#pragma unroll
        for (int nf = 0; nf < 4; nf++) {
            int row = bm + wm + mf * 16 + trow;
            int col = bn + wn + nf * 8 + tcol;
            float2 bs = *(const float2*)(bias + col);
            float v0 = c[mf][nf][0] + bs.x;
            float v1 = c[mf][nf][1] + bs.y;
            float v2 = c[mf][nf][2] + bs.x;
            float v3 = c[mf][nf][3] + bs.y;
            if (OUT_SPLIT) {
                uint32_t hh, ll;
                split2(v0, v1, hh, ll);
                *(uint32_t*)(Ch + (size_t)row * N + col) = hh;
                *(uint32_t*)(Cl + (size_t)row * N + col) = ll;
                split2(v2, v3, hh, ll);
                *(uint32_t*)(Ch + (size_t)(row + 8) * N + col) = hh;
                *(uint32_t*)(Cl + (size_t)(row + 8) * N + col) = ll;
            } else {
                float2 o0; o0.x = v0; o0.y = v1;
                float2 o1; o1.x = v2; o1.y = v3;
                *(float2*)(C + (size_t)row * N + col) = o0;
                *(float2*)(C + (size_t)(row + 8) * N + col) = o1;
            }
        }
    }
}

// ======================= HMMA flash attention =================================
// Grid (SEQ/128, HEADS, BATCH), 256 threads (8 warps x 16 q rows).
// smem: QH(0) QL(18432) | KV buf b at 36864+b*36864:
//       KH(+0) KL(+9216) VH(+18432) VL(+27648); row stride 144B (72 elems)
#define FA_QBYTES 18432
#define FA_KVBUF  36864
#define FA_SMEM   (2 * FA_QBYTES + 2 * FA_KVBUF)   // 110592

__global__ __launch_bounds__(256, 2) void flash_hmma()
{
    extern __shared__ char smem[];
    const uint32_t sb = smem_u32(smem);
    const int tid = threadIdx.x;
    const int lane = tid & 31, wid = tid >> 5;
    const int qb = blockIdx.x * 128;
    const int h  = blockIdx.y;
    const int b  = blockIdx.z;
    const int wq = wid * 16;

    const size_t grow0 = (size_t)b * SEQ;
    const int qcol = h * DH;
    const int kcol = EMB + h * DH;
    const int vcol = 2 * EMB + h * DH;

    // ---- prologue: Q tile (128x64 hi/lo) via cp.async ----
#pragma unroll
    for (int i = 0; i < 4; i++) {
        int cidx = tid + i * 256;          // 0..1023
        int row = cidx >> 3, kc = cidx & 7;
        uint32_t doff = row * 144 + kc * 16;
        size_t go = (grow0 + qb + row) * NQKV + qcol + kc * 8;
        cp16(sb + doff,             g_qkvh + go);
        cp16(sb + FA_QBYTES + doff, g_qkvl + go);
    }
    CP_COMMIT();

    // KV tile loader
    auto load_kv = [&](int t, int buf) {
        const uint32_t kv = sb + 2 * FA_QBYTES + buf * FA_KVBUF;
#pragma unroll
        for (int i = 0; i < 2; i++) {
            int cidx = tid + i * 256;      // 0..511
            int row = cidx >> 3, kc = cidx & 7;
            uint32_t doff = row * 144 + kc * 16;
            size_t gk = (grow0 + t * 64 + row) * NQKV + kcol + kc * 8;
            size_t gv = (grow0 + t * 64 + row) * NQKV + vcol + kc * 8;
            cp16(kv + doff,         g_qkvh + gk);
            cp16(kv + 9216 + doff,  g_qkvl + gk);
            cp16(kv + 18432 + doff, g_qkvh + gv);
            cp16(kv + 27648 + doff, g_qkvl + gv);
        }
    };

    load_kv(0, 0);
    CP_COMMIT();

    // wait for Q, load Q A-frags into registers (persist whole kernel)
    CP_WAIT(1);
    __syncthreads();
    const int a_row = (lane & 7) + ((lane >> 3) & 1) * 8;
    const int a_kc  = ((lane >> 4) & 1) * 8;
    uint32_t qh_f[4][4], ql_f[4][4];
#pragma unroll
    for (int kc = 0; kc < 4; kc++) {
        uint32_t addr = sb + (uint32_t)(wq + a_row) * 144 + (kc * 16 + a_kc) * 2;
        ldsm_x4(qh_f[kc], addr);
        ldsm_x4(ql_f[kc], addr + FA_QBYTES);
    }

    // B-frag lane geometry (K as n8k16 from row-major [key][d])
    const int bk_row = (lane & 7) + ((lane >> 4) & 1) * 8;
    const int bk_kc  = ((lane >> 3) & 1) * 8;
    // V-frag lane geometry (trans, from row-major [key][d])
    const int v_row = (lane & 7) + ((lane >> 3) & 1) * 8;
    const int v_col = ((lane >> 4) & 1) * 8;

    float o[8][4];
#pragma unroll
    for (int i = 0; i < 8; i++)
#pragma unroll
        for (int r = 0; r < 4; r++) o[i][r] = 0.0f;
    // m in log2 domain (already includes 0.125*log2e scale)
    float m0 = -1e30f, m1 = -1e30f, l0 = 0.0f, l1 = 0.0f;
    const float SCL = 0.1803368801111137f;   // 0.125 * log2(e)

    const int NT = SEQ / 64;
    for (int t = 0; t < NT; t++) {
        if (t + 1 < NT) {
            load_kv(t + 1, (t + 1) & 1);
            CP_COMMIT();
            CP_WAIT(1);
        } else {
            CP_WAIT(0);
        }
        __syncthreads();
        const uint32_t kvb = sb + 2 * FA_QBYTES + (t & 1) * FA_KVBUF;

        // ---- S = Q K^T (split, fp32 accum); term-major, reuse gap = 8 MMAs ----
        float s[8][4];
#pragma unroll
        for (int i = 0; i < 8; i++)
#pragma unroll
            for (int r = 0; r < 4; r++) s[i][r] = 0.0f;
#pragma unroll
        for (int kc = 0; kc < 4; kc++) {
            uint32_t kf[4][4];
#pragma unroll
            for (int np = 0; np < 4; np++)
                ldsm_x4(kf[np], kvb + (uint32_t)(np * 16 + bk_row) * 144 + (kc * 16 + bk_kc) * 2);
#pragma unroll
            for (int np = 0; np < 4; np++) {
                mma_bf16(s[np * 2],     qh_f[kc], kf[np]);
                mma_bf16(s[np * 2 + 1], qh_f[kc], kf[np] + 2);
            }
#pragma unroll
            for (int np = 0; np < 4; np++) {
                mma_bf16(s[np * 2],     ql_f[kc], kf[np]);
                mma_bf16(s[np * 2 + 1], ql_f[kc], kf[np] + 2);
            }
#pragma unroll
            for (int np = 0; np < 4; np++)
                ldsm_x4(kf[np], kvb + 9216 + (uint32_t)(np * 16 + bk_row) * 144 + (kc * 16 + bk_kc) * 2);
#pragma unroll
            for (int np = 0; np < 4; np++) {
                mma_bf16(s[np * 2],     qh_f[kc], kf[np]);
                mma_bf16(s[np * 2 + 1], qh_f[kc], kf[np] + 2);
            }
        }

        // ---- online softmax in log2 domain ----
        float rm0 = -1e30f, rm1 = -1e30f;
#pragma unroll
        for (int nf = 0; nf < 8; nf++) {
            rm0 = fmaxf(rm0, fmaxf(s[nf][0], s[nf][1]));
            rm1 = fmaxf(rm1, fmaxf(s[nf][2], s[nf][3]));
        }
        rm0 = fmaxf(rm0, __shfl_xor_sync(0xffffffffu, rm0, 1));
        rm0 = fmaxf(rm0, __shfl_xor_sync(0xffffffffu, rm0, 2));
        rm1 = fmaxf(rm1, __shfl_xor_sync(0xffffffffu, rm1, 1));
        rm1 = fmaxf(rm1, __shfl_xor_sync(0xffffffffu, rm1, 2));
        float mn0 = fmaxf(m0, rm0 * SCL);
        float mn1 = fmaxf(m1, rm1 * SCL);
        float corr0 = ex2f(m0 - mn0);
        float corr1 = ex2f(m1 - mn1);
        m0 = mn0; m1 = mn1;
        float sum0 = 0.0f, sum1 = 0.0f;
#pragma unroll
        for (int nf = 0; nf < 8; nf++) {
            s[nf][0] = ex2f(fmaf(s[nf][0], SCL, -mn0));
            s[nf][1] = ex2f(fmaf(s[nf][1], SCL, -mn0));
            s[nf][2] = ex2f(fmaf(s[nf][2], SCL, -mn1));
            s[nf][3] = ex2f(fmaf(s[nf][3], SCL, -mn1));
            sum0 += s[nf][0] + s[nf][1];
            sum1 += s[nf][2] + s[nf][3];
        }
        sum0 += __shfl_xor_sync(0xffffffffu, sum0, 1);
        sum0 += __shfl_xor_sync(0xffffffffu, sum0, 2);
        sum1 += __shfl_xor_sync(0xffffffffu, sum1, 1);
        sum1 += __shfl_xor_sync(0xffffffffu, sum1, 2);
        l0 = l0 * corr0 + sum0;
        l1 = l1 * corr1 + sum1;
        // rescale O
#pragma unroll
        for (int nf = 0; nf < 8; nf++) {
            o[nf][0] *= corr0; o[nf][1] *= corr0;
            o[nf][2] *= corr1; o[nf][3] *= corr1;
        }
        // ---- P -> bf16 split A-frags (register-only relayout) ----
        uint32_t ph[4][4], pl[4][4];
#pragma unroll
        for (int kc = 0; kc < 4; kc++) {
            split2(s[2 * kc][0],     s[2 * kc][1],     ph[kc][0], pl[kc][0]);
            split2(s[2 * kc][2],     s[2 * kc][3],     ph[kc][1], pl[kc][1]);
            split2(s[2 * kc + 1][0], s[2 * kc + 1][1], ph[kc][2], pl[kc][2]);
            split2(s[2 * kc + 1][2], s[2 * kc + 1][3], ph[kc][3], pl[kc][3]);
        }

        // ---- O += P V (split); term-major, reuse gap = 8 MMAs ----
#pragma unroll
        for (int kc = 0; kc < 4; kc++) {
            uint32_t vf[4][4];
#pragma unroll
            for (int np = 0; np < 4; np++)
                ldsm_x4_t(vf[np], kvb + 18432 + (uint32_t)(kc * 16 + v_row) * 144 + (np * 16 + v_col) * 2);
#pragma unroll
            for (int np = 0; np < 4; np++) {
                mma_bf16(o[np * 2],     ph[kc], vf[np]);
                mma_bf16(o[np * 2 + 1], ph[kc], vf[np] + 2);
            }
#pragma unroll
            for (int np = 0; np < 4; np++) {
                mma_bf16(o[np * 2],     pl[kc], vf[np]);
                mma_bf16(o[np * 2 + 1], pl[kc], vf[np] + 2);
            }
#pragma unroll
            for (int np = 0; np < 4; np++)
                ldsm_x4_t(vf[np], kvb + 27648 + (uint32_t)(kc * 16 + v_row) * 144 + (np * 16 + v_col) * 2);
#pragma unroll
            for (int np = 0; np < 4; np++) {
                mma_bf16(o[np * 2],     ph[kc], vf[np]);
                mma_bf16(o[np * 2 + 1], ph[kc], vf[np] + 2);
            }
        }
        __syncthreads();
    }

    // ---- epilogue: normalize, split to bf16, write g_yh/g_yl ----
    float inv0 = 1.0f / l0, inv1 = 1.0f / l1;
    size_t row0 = grow0 + qb + wq + (lane >> 2);
#pragma unroll
    for (int nf = 0; nf < 8; nf++) {
        int col = h * DH + nf * 8 + (lane & 3) * 2;
        uint32_t hh, ll;
        split2(o[nf][0] * inv0, o[nf][1] * inv0, hh, ll);
        *(uint32_t*)(g_yh + row0 * EMB + col) = hh;
        *(uint32_t*)(g_yl + row0 * EMB + col) = ll;
        split2(o[nf][2] * inv1, o[nf][3] * inv1, hh, ll);
        *(uint32_t*)(g_yh + (row0 + 8) * EMB + col) = hh;
        *(uint32_t*)(g_yl + (row0 + 8) * EMB + col) = ll;
    }
}

// ======================= launch ===============================================
extern "C" void kernel_launch(void* const* d_in, const int* in_sizes, int n_in,
                              void* d_out, int out_size)
{
    const float* x  = (const float*)d_in[0];
    const float* Wa = (const float*)d_in[1];
    const float* ba = (const float*)d_in[2];
    const float* Wo = (const float*)d_in[3];
    const float* bo = (const float*)d_in[4];
    float* out = (float*)d_out;

    cudaFuncSetAttribute(hgemm<1>, cudaFuncAttributeMaxDynamicSharedMemorySize, GE_SMEM);
    cudaFuncSetAttribute(hgemm<0>, cudaFuncAttributeMaxDynamicSharedMemorySize, GE_SMEM);
    cudaFuncSetAttribute(flash_hmma, cudaFuncAttributeMaxDynamicSharedMemorySize, FA_SMEM);

    __nv_bfloat16 *xh, *xl, *qh, *ql, *yh, *yl, *wah, *wal, *woh, *wol;
    cudaGetSymbolAddress((void**)&xh,  g_xh);
    cudaGetSymbolAddress((void**)&xl,  g_xl);
    cudaGetSymbolAddress((void**)&qh,  g_qkvh);
    cudaGetSymbolAddress((void**)&ql,  g_qkvl);
    cudaGetSymbolAddress((void**)&yh,  g_yh);
    cudaGetSymbolAddress((void**)&yl,  g_yl);
    cudaGetSymbolAddress((void**)&wah, g_wah);
    cudaGetSymbolAddress((void**)&wal, g_wal);
    cudaGetSymbolAddress((void**)&woh, g_woh);
    cudaGetSymbolAddress((void**)&wol, g_wol);

    // input/weight splits
    conv_split<<<(MROWS * EMB / 4 + 255) / 256, 256>>>(x, xh, xl, MROWS * EMB);
    conv_w_t<<<(EMB * NQKV + 255) / 256, 256>>>(Wa, wah, wal, EMB, NQKV);
    conv_w_t<<<(EMB * EMB + 255) / 256, 256>>>(Wo, woh, wol, EMB, EMB);

    // QKV projection -> bf16 hi/lo (bias added in fp32)
    dim3 g1(NQKV / 128, MROWS / 128);   // (12, 64)
    hgemm<1><<<g1, 256, GE_SMEM>>>(xh, xl, wah, wal, ba, nullptr, qh, ql, NQKV, EMB);

    // attention
    dim3 g2(SEQ / 128, HEADS, BATCH);   // (16, 8, 4)
    flash_hmma<<<g2, 256, FA_SMEM>>>();

    // output projection -> fp32 out
    dim3 g3(EMB / 128, MROWS / 128);    // (4, 64)
    hgemm<0><<<g3, 256, GE_SMEM>>>(yh, yl, woh, wol, bo, out, nullptr, nullptr, EMB, EMB);
}

// round 15
// speedup vs baseline: 1.0030x; 1.0030x over previous
#include <cuda_runtime.h>
#include <cuda_bf16.h>
#include <stdint.h>

// Problem constants
#define BATCH   4
#define SEQ     2048
#define EMB     512
#define HEADS   8
#define DH      64
#define MROWS   (BATCH * SEQ)     // 8192
#define NQKV    (3 * EMB)         // 1536

// ======================= scratch (__device__ globals) =========================
__device__ __nv_bfloat16 g_xh[(size_t)MROWS * EMB];
__device__ __nv_bfloat16 g_xl[(size_t)MROWS * EMB];
__device__ __nv_bfloat16 g_qkvh[(size_t)MROWS * NQKV];
__device__ __nv_bfloat16 g_qkvl[(size_t)MROWS * NQKV];
__device__ __nv_bfloat16 g_yh[(size_t)MROWS * EMB];
__device__ __nv_bfloat16 g_yl[(size_t)MROWS * EMB];
__device__ __nv_bfloat16 g_wah[(size_t)NQKV * EMB];   // W_attn^T [1536,512]
__device__ __nv_bfloat16 g_wal[(size_t)NQKV * EMB];
__device__ __nv_bfloat16 g_woh[(size_t)EMB * EMB];    // W_out^T [512,512]
__device__ __nv_bfloat16 g_wol[(size_t)EMB * EMB];

// ======================= helpers ==============================================
__device__ __forceinline__ uint32_t smem_u32(const void* p) {
    uint32_t a;
    asm("{ .reg .u64 t; cvta.to.shared.u64 t, %1; cvt.u32.u64 %0, t; }" : "=r"(a) : "l"(p));
    return a;
}
__device__ __forceinline__ void cp16(uint32_t dst, const void* src) {
    asm volatile("cp.async.cg.shared.global [%0], [%1], 16;" :: "r"(dst), "l"(src));
}
#define CP_COMMIT() asm volatile("cp.async.commit_group;" ::: "memory")
#define CP_WAIT(n)  asm volatile("cp.async.wait_group %0;" :: "n"(n) : "memory")

__device__ __forceinline__ void ldsm_x4(uint32_t* r, uint32_t addr) {
    asm volatile("ldmatrix.sync.aligned.m8n8.x4.shared.b16 {%0,%1,%2,%3}, [%4];"
                 : "=r"(r[0]), "=r"(r[1]), "=r"(r[2]), "=r"(r[3]) : "r"(addr));
}
__device__ __forceinline__ void ldsm_x4_t(uint32_t* r, uint32_t addr) {
    asm volatile("ldmatrix.sync.aligned.m8n8.x4.trans.shared.b16 {%0,%1,%2,%3}, [%4];"
                 : "=r"(r[0]), "=r"(r[1]), "=r"(r[2]), "=r"(r[3]) : "r"(addr));
}
__device__ __forceinline__ void mma_bf16(float* c, const uint32_t* a, const uint32_t* b) {
    asm volatile("mma.sync.aligned.m16n8k16.row.col.f32.bf16.bf16.f32 "
                 "{%0,%1,%2,%3}, {%4,%5,%6,%7}, {%8,%9}, {%0,%1,%2,%3};"
                 : "+f"(c[0]), "+f"(c[1]), "+f"(c[2]), "+f"(c[3])
                 : "r"(a[0]), "r"(a[1]), "r"(a[2]), "r"(a[3]), "r"(b[0]), "r"(b[1]));
}
__device__ __forceinline__ float ex2f(float x) {
    float y;
    asm("ex2.approx.f32 %0, %1;" : "=f"(y) : "f"(x));
    return y;
}
// split pair of fp32 into bf16 hi (packed) + bf16 lo residual (packed)
__device__ __forceinline__ void split2(float v0, float v1, uint32_t& hh, uint32_t& ll) {
    __nv_bfloat162 h2, l2;
    h2.x = __float2bfloat16(v0);
    h2.y = __float2bfloat16(v1);
    l2.x = __float2bfloat16(v0 - __bfloat162float(h2.x));
    l2.y = __float2bfloat16(v1 - __bfloat162float(h2.y));
    hh = *(uint32_t*)&h2;
    ll = *(uint32_t*)&l2;
}

// ======================= conversion kernels ===================================
__global__ __launch_bounds__(256) void conv_split(const float* __restrict__ in,
                                                  __nv_bfloat16* __restrict__ h,
                                                  __nv_bfloat16* __restrict__ l, int n) {
    int i = (blockIdx.x * blockDim.x + threadIdx.x) * 4;
    if (i >= n) return;
    float4 v = *(const float4*)(in + i);
    uint32_t h0, l0, h1, l1;
    split2(v.x, v.y, h0, l0);
    split2(v.z, v.w, h1, l1);
    *(uint32_t*)(h + i)     = h0;
    *(uint32_t*)(h + i + 2) = h1;
    *(uint32_t*)(l + i)     = l0;
    *(uint32_t*)(l + i + 2) = l1;
}

// W [K,N] row-major -> W^T [N,K] split hi/lo, 32x32 smem-tiled transpose
__global__ __launch_bounds__(256) void conv_w_t(const float* __restrict__ W,
                                                __nv_bfloat16* __restrict__ Th,
                                                __nv_bfloat16* __restrict__ Tl,
                                                int K, int N) {
    __shared__ float tile[32][33];
    const int tx = threadIdx.x & 31, ty = threadIdx.x >> 5;   // 32 x 8
    const int n0 = blockIdx.x * 32, k0 = blockIdx.y * 32;
#pragma unroll
    for (int i = 0; i < 4; i++) {
        int k = k0 + ty + i * 8;
        tile[ty + i * 8][tx] = W[(size_t)k * N + n0 + tx];    // coalesced read
    }
    __syncthreads();
#pragma unroll
    for (int i = 0; i < 4; i++) {
        int n = n0 + ty + i * 8;
        float v = tile[tx][ty + i * 8];
        __nv_bfloat16 h = __float2bfloat16(v);
        size_t o = (size_t)n * K + k0 + tx;                   // coalesced write
        Th[o] = h;
        Tl[o] = __float2bfloat16(v - __bfloat162float(h));
    }
}

// ======================= split-bf16 HMMA GEMM =================================
// C[M,N] = (Ah+Al)[M,K] @ (Bh+Bl)[N,K]^T + bias
// BM=256, BN=128, BK=32, 512 threads (16 warps: 4m x 4n, warp tile 64x32)
// 3-stage cp.async pipeline. Per stage: Ah(0,20480B) Al(20480) Bh(40960,10240B)
// Bl(51200); stage stride 61440; row stride 80B.
#define GE_STAGE 61440
#define GE_SMEM  (3 * GE_STAGE)   // 184320

template<int OUT_SPLIT>
__global__ __launch_bounds__(512, 1) void hgemm(
    const __nv_bfloat16* __restrict__ Ah, const __nv_bfloat16* __restrict__ Al,
    const __nv_bfloat16* __restrict__ Bh, const __nv_bfloat16* __restrict__ Bl,
    const float* __restrict__ bias,
    float* __restrict__ C, __nv_bfloat16* __restrict__ Ch, __nv_bfloat16* __restrict__ Cl,
    int N, int K)
{
    extern __shared__ char smem[];
    const uint32_t sb = smem_u32(smem);
    const int tid = threadIdx.x;
    const int lane = tid & 31, wid = tid >> 5;
    const int bm = blockIdx.y * 256, bn = blockIdx.x * 128;
    const int wm = (wid >> 2) * 64, wn = (wid & 3) * 32;

    // ldmatrix lane geometry
    const int a_row = (lane & 7) + ((lane >> 3) & 1) * 8;
    const int a_kc  = ((lane >> 4) & 1) * 8;
    const int b_row = (lane & 7) + ((lane >> 4) & 1) * 8;
    const int b_kc  = ((lane >> 3) & 1) * 8;

    float c[4][4][4];
#pragma unroll
    for (int i = 0; i < 4; i++)
#pragma unroll
        for (int j = 0; j < 4; j++)
#pragma unroll
            for (int r = 0; r < 4; r++) c[i][j][r] = 0.0f;

    const int nstage = K >> 5;

    // stage loader: A 2048 cp16, B 1024 cp16 (6 per thread)
    auto load_stage = [&](int k0, int buf) {
        const uint32_t s0 = sb + buf * GE_STAGE;
#pragma unroll
        for (int i = 0; i < 2; i++) {
            int slot = tid + i * 512;          // 0..1023
            int row = slot >> 2, kc = slot & 3;
            uint32_t doff = row * 80 + kc * 16;
            size_t ao = (size_t)(bm + row) * K + k0 + kc * 8;
            cp16(s0 + doff,         Ah + ao);
            cp16(s0 + 20480 + doff, Al + ao);
        }
        {
            int row = tid >> 2, kc = tid & 3;  // 0..127 rows
            uint32_t doff = row * 80 + kc * 16;
            size_t bo = (size_t)(bn + row) * K + k0 + kc * 8;
            cp16(s0 + 40960 + doff, Bh + bo);
            cp16(s0 + 51200 + doff, Bl + bo);
        }
    };

    load_stage(0, 0);
    CP_COMMIT();
    load_stage(32, 1);
    CP_COMMIT();

    for (int s = 0; s < nstage; s++) {
        if (s == nstage - 1) { CP_WAIT(0); } else { CP_WAIT(1); }
        __syncthreads();
        if (s + 2 < nstage) {
            load_stage((s + 2) * 32, (s + 2) % 3);
            CP_COMMIT();
        }
        const uint32_t s0 = sb + (s % 3) * GE_STAGE;
#pragma unroll
        for (int kk = 0; kk < 2; kk++) {
            uint32_t bh[4][2], bl[4][2];
#pragma unroll
            for (int np = 0; np < 2; np++) {
                uint32_t r4[4];
                uint32_t addr = s0 + 40960 + (uint32_t)(wn + np * 16 + b_row) * 80 + (kk * 16 + b_kc) * 2;
                ldsm_x4(r4, addr);
                bh[np * 2][0] = r4[0]; bh[np * 2][1] = r4[1];
                bh[np * 2 + 1][0] = r4[2]; bh[np * 2 + 1][1] = r4[3];
                ldsm_x4(r4, addr + 10240);
                bl[np * 2][0] = r4[0]; bl[np * 2][1] = r4[1];
                bl[np * 2 + 1][0] = r4[2]; bl[np * 2 + 1][1] = r4[3];
            }
#pragma unroll
            for (int mf = 0; mf < 4; mf++) {
                uint32_t ah[4], al[4];
                uint32_t addr = s0 + (uint32_t)(wm + mf * 16 + a_row) * 80 + (kk * 16 + a_kc) * 2;
                ldsm_x4(ah, addr);
                ldsm_x4(al, addr + 20480);
#pragma unroll
                for (int nf = 0; nf < 4; nf++) mma_bf16(c[mf][nf], ah, bh[nf]);
#pragma unroll
                for (int nf = 0; nf < 4; nf++) mma_bf16(c[mf][nf], ah, bl[nf]);
#pragma unroll
                for (int nf = 0; nf < 4; nf++) mma_bf16(c[mf][nf], al, bh[nf]);
            }
        }
    }

    // epilogue
    const int trow = lane >> 2, tcol = (lane & 3) * 2;
#pragma unroll
    for (int mf = 0; mf < 4; mf++) {
#pragma unroll
        for (int nf = 0; nf < 4; nf++) {
            int row = bm + wm + mf * 16 + trow;
            int col = bn + wn + nf * 8 + tcol;
            float2 bs = *(const float2*)(bias + col);
            float v0 = c[mf][nf][0] + bs.x;
            float v1 = c[mf][nf][1] + bs.y;
            float v2 = c[mf][nf][2] + bs.x;
            float v3 = c[mf][nf][3] + bs.y;
            if (OUT_SPLIT) {
                uint32_t hh, ll;
                split2(v0, v1, hh, ll);
                *(uint32_t*)(Ch + (size_t)row * N + col) = hh;
                *(uint32_t*)(Cl + (size_t)row * N + col) = ll;
                split2(v2, v3, hh, ll);
                *(uint32_t*)(Ch + (size_t)(row + 8) * N + col) = hh;
                *(uint32_t*)(Cl + (size_t)(row + 8) * N + col) = ll;
            } else {
                float2 o0; o0.x = v0; o0.y = v1;
                float2 o1; o1.x = v2; o1.y = v3;
                *(float2*)(C + (size_t)row * N + col) = o0;
                *(float2*)(C + (size_t)(row + 8) * N + col) = o1;
            }
        }
    }
}

// ======================= HMMA flash attention =================================
// Grid (SEQ/128, HEADS, BATCH), 256 threads (8 warps x 16 q rows).
// smem: QH(0) QL(18432) | KV buf b at 36864+b*36864:
//       KH(+0) KL(+9216) VH(+18432) VL(+27648); row stride 144B
#define FA_QBYTES 18432
#define FA_KVBUF  36864
#define FA_SMEM   (2 * FA_QBYTES + 2 * FA_KVBUF)   // 110592

__global__ __launch_bounds__(256, 2) void flash_hmma()
{
    extern __shared__ char smem[];
    const uint32_t sb = smem_u32(smem);
    const int tid = threadIdx.x;
    const int lane = tid & 31, wid = tid >> 5;
    const int qb = blockIdx.x * 128;
    const int h  = blockIdx.y;
    const int b  = blockIdx.z;
    const int wq = wid * 16;

    const size_t grow0 = (size_t)b * SEQ;
    const int qcol = h * DH;
    const int kcol = EMB + h * DH;
    const int vcol = 2 * EMB + h * DH;

    // ---- prologue: Q tile (128x64 hi/lo) via cp.async ----
#pragma unroll
    for (int i = 0; i < 4; i++) {
        int cidx = tid + i * 256;          // 0..1023
        int row = cidx >> 3, kc = cidx & 7;
        uint32_t doff = row * 144 + kc * 16;
        size_t go = (grow0 + qb + row) * NQKV + qcol + kc * 8;
        cp16(sb + doff,             g_qkvh + go);
        cp16(sb + FA_QBYTES + doff, g_qkvl + go);
    }
    CP_COMMIT();

    // KV tile loader
    auto load_kv = [&](int t, int buf) {
        const uint32_t kv = sb + 2 * FA_QBYTES + buf * FA_KVBUF;
#pragma unroll
        for (int i = 0; i < 2; i++) {
            int cidx = tid + i * 256;      // 0..511
            int row = cidx >> 3, kc = cidx & 7;
            uint32_t doff = row * 144 + kc * 16;
            size_t gk = (grow0 + t * 64 + row) * NQKV + kcol + kc * 8;
            size_t gv = (grow0 + t * 64 + row) * NQKV + vcol + kc * 8;
            cp16(kv + doff,         g_qkvh + gk);
            cp16(kv + 9216 + doff,  g_qkvl + gk);
            cp16(kv + 18432 + doff, g_qkvh + gv);
            cp16(kv + 27648 + doff, g_qkvl + gv);
        }
    };

    load_kv(0, 0);
    CP_COMMIT();

    // wait for Q (kv0 may still be in flight), load Q A-frags into registers
    CP_WAIT(1);
    __syncthreads();
    const int a_row = (lane & 7) + ((lane >> 3) & 1) * 8;
    const int a_kc  = ((lane >> 4) & 1) * 8;
    uint32_t qh_f[4][4], ql_f[4][4];
#pragma unroll
    for (int kc = 0; kc < 4; kc++) {
        uint32_t addr = sb + (uint32_t)(wq + a_row) * 144 + (kc * 16 + a_kc) * 2;
        ldsm_x4(qh_f[kc], addr);
        ldsm_x4(ql_f[kc], addr + FA_QBYTES);
    }

    // B-frag lane geometry (K as n8k16 from row-major [key][d])
    const int bk_row = (lane & 7) + ((lane >> 4) & 1) * 8;
    const int bk_kc  = ((lane >> 3) & 1) * 8;
    // V-frag lane geometry (trans, from row-major [key][d])
    const int v_row = (lane & 7) + ((lane >> 3) & 1) * 8;
    const int v_col = ((lane >> 4) & 1) * 8;

    float o[8][4];
#pragma unroll
    for (int i = 0; i < 8; i++)
#pragma unroll
        for (int r = 0; r < 4; r++) o[i][r] = 0.0f;
    // m in log2 domain (already includes 0.125*log2e scale)
    float m0 = -1e30f, m1 = -1e30f, l0 = 0.0f, l1 = 0.0f;
    const float SCL = 0.1803368801111137f;   // 0.125 * log2(e)

    const int NT = SEQ / 64;
    for (int t = 0; t < NT; t++) {
        CP_WAIT(0);           // tile t resident
        __syncthreads();      // all warps done reading buffer t-1
        if (t + 1 < NT) {     // prefetch t+1 into the buffer t-1 vacated
            load_kv(t + 1, (t + 1) & 1);
            CP_COMMIT();
        }
        const uint32_t kvb = sb + 2 * FA_QBYTES + (t & 1) * FA_KVBUF;

        // ---- S = Q K^T (split, fp32 accum); term-major, reuse gap = 8 MMAs ----
        float s[8][4];
#pragma unroll
        for (int i = 0; i < 8; i++)
#pragma unroll
            for (int r = 0; r < 4; r++) s[i][r] = 0.0f;
#pragma unroll
        for (int kc = 0; kc < 4; kc++) {
            uint32_t kf[4][4];
#pragma unroll
            for (int np = 0; np < 4; np++)
                ldsm_x4(kf[np], kvb + (uint32_t)(np * 16 + bk_row) * 144 + (kc * 16 + bk_kc) * 2);
#pragma unroll
            for (int np = 0; np < 4; np++) {
                mma_bf16(s[np * 2],     qh_f[kc], kf[np]);
                mma_bf16(s[np * 2 + 1], qh_f[kc], kf[np] + 2);
            }
#pragma unroll
            for (int np = 0; np < 4; np++) {
                mma_bf16(s[np * 2],     ql_f[kc], kf[np]);
                mma_bf16(s[np * 2 + 1], ql_f[kc], kf[np] + 2);
            }
#pragma unroll
            for (int np = 0; np < 4; np++)
                ldsm_x4(kf[np], kvb + 9216 + (uint32_t)(np * 16 + bk_row) * 144 + (kc * 16 + bk_kc) * 2);
#pragma unroll
            for (int np = 0; np < 4; np++) {
                mma_bf16(s[np * 2],     qh_f[kc], kf[np]);
                mma_bf16(s[np * 2 + 1], qh_f[kc], kf[np] + 2);
            }
        }

        // ---- online softmax in log2 domain ----
        float rm0 = -1e30f, rm1 = -1e30f;
#pragma unroll
        for (int nf = 0; nf < 8; nf++) {
            rm0 = fmaxf(rm0, fmaxf(s[nf][0], s[nf][1]));
            rm1 = fmaxf(rm1, fmaxf(s[nf][2], s[nf][3]));
        }
        rm0 = fmaxf(rm0, __shfl_xor_sync(0xffffffffu, rm0, 1));
        rm0 = fmaxf(rm0, __shfl_xor_sync(0xffffffffu, rm0, 2));
        rm1 = fmaxf(rm1, __shfl_xor_sync(0xffffffffu, rm1, 1));
        rm1 = fmaxf(rm1, __shfl_xor_sync(0xffffffffu, rm1, 2));
        float mn0 = fmaxf(m0, rm0 * SCL);
        float mn1 = fmaxf(m1, rm1 * SCL);
        float corr0 = ex2f(m0 - mn0);
        float corr1 = ex2f(m1 - mn1);
        m0 = mn0; m1 = mn1;
        float sum0 = 0.0f, sum1 = 0.0f;
#pragma unroll
        for (int nf = 0; nf < 8; nf++) {
            s[nf][0] = ex2f(fmaf(s[nf][0], SCL, -mn0));
            s[nf][1] = ex2f(fmaf(s[nf][1], SCL, -mn0));
            s[nf][2] = ex2f(fmaf(s[nf][2], SCL, -mn1));
            s[nf][3] = ex2f(fmaf(s[nf][3], SCL, -mn1));
            sum0 += s[nf][0] + s[nf][1];
            sum1 += s[nf][2] + s[nf][3];
        }
        sum0 += __shfl_xor_sync(0xffffffffu, sum0, 1);
        sum0 += __shfl_xor_sync(0xffffffffu, sum0, 2);
        sum1 += __shfl_xor_sync(0xffffffffu, sum1, 1);
        sum1 += __shfl_xor_sync(0xffffffffu, sum1, 2);
        l0 = l0 * corr0 + sum0;
        l1 = l1 * corr1 + sum1;
        // rescale O
#pragma unroll
        for (int nf = 0; nf < 8; nf++) {
            o[nf][0] *= corr0; o[nf][1] *= corr0;
            o[nf][2] *= corr1; o[nf][3] *= corr1;
        }
        // ---- P -> bf16 split A-frags (register-only relayout) ----
        uint32_t ph[4][4], pl[4][4];
#pragma unroll
        for (int kc = 0; kc < 4; kc++) {
            split2(s[2 * kc][0],     s[2 * kc][1],     ph[kc][0], pl[kc][0]);
            split2(s[2 * kc][2],     s[2 * kc][3],     ph[kc][1], pl[kc][1]);
            split2(s[2 * kc + 1][0], s[2 * kc + 1][1], ph[kc][2], pl[kc][2]);
            split2(s[2 * kc + 1][2], s[2 * kc + 1][3], ph[kc][3], pl[kc][3]);
        }

        // ---- O += P V (split); term-major, reuse gap = 8 MMAs ----
#pragma unroll
        for (int kc = 0; kc < 4; kc++) {
            uint32_t vf[4][4];
#pragma unroll
            for (int np = 0; np < 4; np++)
                ldsm_x4_t(vf[np], kvb + 18432 + (uint32_t)(kc * 16 + v_row) * 144 + (np * 16 + v_col) * 2);
#pragma unroll
            for (int np = 0; np < 4; np++) {
                mma_bf16(o[np * 2],     ph[kc], vf[np]);
                mma_bf16(o[np * 2 + 1], ph[kc], vf[np] + 2);
            }
#pragma unroll
            for (int np = 0; np < 4; np++) {
                mma_bf16(o[np * 2],     pl[kc], vf[np]);
                mma_bf16(o[np * 2 + 1], pl[kc], vf[np] + 2);
            }
#pragma unroll
            for (int np = 0; np < 4; np++)
                ldsm_x4_t(vf[np], kvb + 27648 + (uint32_t)(kc * 16 + v_row) * 144 + (np * 16 + v_col) * 2);
#pragma unroll
            for (int np = 0; np < 4; np++) {
                mma_bf16(o[np * 2],     ph[kc], vf[np]);
                mma_bf16(o[np * 2 + 1], ph[kc], vf[np] + 2);
            }
        }
    }

    // ---- epilogue: normalize, split to bf16, write g_yh/g_yl ----
    float inv0 = 1.0f / l0, inv1 = 1.0f / l1;
    size_t row0 = grow0 + qb + wq + (lane >> 2);
#pragma unroll
    for (int nf = 0; nf < 8; nf++) {
        int col = h * DH + nf * 8 + (lane & 3) * 2;
        uint32_t hh, ll;
        split2(o[nf][0] * inv0, o[nf][1] * inv0, hh, ll);
        *(uint32_t*)(g_yh + row0 * EMB + col) = hh;
        *(uint32_t*)(g_yl + row0 * EMB + col) = ll;
        split2(o[nf][2] * inv1, o[nf][3] * inv1, hh, ll);
        *(uint32_t*)(g_yh + (row0 + 8) * EMB + col) = hh;
        *(uint32_t*)(g_yl + (row0 + 8) * EMB + col) = ll;
    }
}

// ======================= launch ===============================================
extern "C" void kernel_launch(void* const* d_in, const int* in_sizes, int n_in,
                              void* d_out, int out_size)
{
    const float* x  = (const float*)d_in[0];
    const float* Wa = (const float*)d_in[1];
    const float* ba = (const float*)d_in[2];
    const float* Wo = (const float*)d_in[3];
    const float* bo = (const float*)d_in[4];
    float* out = (float*)d_out;

    cudaFuncSetAttribute(hgemm<1>, cudaFuncAttributeMaxDynamicSharedMemorySize, GE_SMEM);
    cudaFuncSetAttribute(hgemm<0>, cudaFuncAttributeMaxDynamicSharedMemorySize, GE_SMEM);
    cudaFuncSetAttribute(flash_hmma, cudaFuncAttributeMaxDynamicSharedMemorySize, FA_SMEM);

    __nv_bfloat16 *xh, *xl, *qh, *ql, *yh, *yl, *wah, *wal, *woh, *wol;
    cudaGetSymbolAddress((void**)&xh,  g_xh);
    cudaGetSymbolAddress((void**)&xl,  g_xl);
    cudaGetSymbolAddress((void**)&qh,  g_qkvh);
    cudaGetSymbolAddress((void**)&ql,  g_qkvl);
    cudaGetSymbolAddress((void**)&yh,  g_yh);
    cudaGetSymbolAddress((void**)&yl,  g_yl);
    cudaGetSymbolAddress((void**)&wah, g_wah);
    cudaGetSymbolAddress((void**)&wal, g_wal);
    cudaGetSymbolAddress((void**)&woh, g_woh);
    cudaGetSymbolAddress((void**)&wol, g_wol);

    // input/weight splits
    conv_split<<<(MROWS * EMB / 4 + 255) / 256, 256>>>(x, xh, xl, MROWS * EMB);
    {
        dim3 gt(NQKV / 32, EMB / 32);
        conv_w_t<<<gt, 256>>>(Wa, wah, wal, EMB, NQKV);
        dim3 gt2(EMB / 32, EMB / 32);
        conv_w_t<<<gt2, 256>>>(Wo, woh, wol, EMB, EMB);
    }

    // QKV projection -> bf16 hi/lo (bias added in fp32)
    dim3 g1(NQKV / 128, MROWS / 256);   // (12, 32)
    hgemm<1><<<g1, 512, GE_SMEM>>>(xh, xl, wah, wal, ba, nullptr, qh, ql, NQKV, EMB);

    // attention
    dim3 g2(SEQ / 128, HEADS, BATCH);   // (16, 8, 4)
    flash_hmma<<<g2, 256, FA_SMEM>>>();

    // output projection -> fp32 out (single wave: 128 CTAs)
    dim3 g3(EMB / 128, MROWS / 256);    // (4, 32)
    hgemm<0><<<g3, 512, GE_SMEM>>>(yh, yl, woh, wol, bo, out, nullptr, nullptr, EMB, EMB);
}